// round 1
// baseline (speedup 1.0000x reference)
#include <cuda_runtime.h>
#include <cstdint>

#define FULLMASK 0xffffffffu

// scratch for pooled max (pre-bias, pre-relu): [B, 10], B = 20000
__device__ float g_pooled[20000 * 10];

__device__ __forceinline__ unsigned long long pk2(float x, float y) {
    unsigned long long r;
    asm("mov.b64 %0, {%1, %2};" : "=l"(r) : "f"(x), "f"(y));
    return r;
}
__device__ __forceinline__ float2 upk2(unsigned long long p) {
    float2 t;
    asm("mov.b64 {%0, %1}, %2;" : "=f"(t.x), "=f"(t.y) : "l"(p));
    return t;
}
__device__ __forceinline__ void fma2(unsigned long long& d, unsigned long long a, unsigned long long b) {
    asm("fma.rn.f32x2 %0, %1, %2, %0;" : "+l"(d) : "l"(a), "l"(b));
}

// ---------------------------------------------------------------------------
// Kernel 1: neighbor MLP (D=256 -> H=10) + max-pool over N=32 neighbors.
// One block = 256 threads = 8 warps. Warp w handles neighbors {w, w+8, w+16, w+24}.
// Each lane owns 8 d-values: {lane*4..+3, 128+lane*4..+3} (fully coalesced float4s).
// W1 held in registers (packed f32x2 over the H dim). Paired butterfly reduce:
// two neighbors share the offset-8/4/2/1 stages via warp-half split.
// ---------------------------------------------------------------------------
__global__ void __launch_bounds__(256, 1)
k1_neigh_pool(const float* __restrict__ neigh, const float* __restrict__ W1, int B)
{
    __shared__ float sbuf[2560];   // W1 staging, then reused as 16x10 warp-max buffer
    const int tid  = threadIdx.x;
    const int lane = tid & 31;
    const int warp = tid >> 5;

    // stage W1 (256x10) into smem once per block (coalesced), then to registers
    for (int i = tid; i < 2560; i += 256) sbuf[i] = W1[i];
    __syncthreads();

    unsigned long long w1p[8][5];
    #pragma unroll
    for (int i = 0; i < 8; i++) {
        int d = (i < 4) ? (lane * 4 + i) : (128 + lane * 4 + (i - 4));
        #pragma unroll
        for (int jp = 0; jp < 5; jp++) {
            float2 t = *(const float2*)&sbuf[d * 10 + 2 * jp];
            w1p[i][jp] = pk2(t.x, t.y);
        }
    }
    __syncthreads();
    float* smax = sbuf;  // reuse: [16][10]

    for (int b = blockIdx.x; b < B; b += gridDim.x) {
        const float* nb = neigh + (size_t)b * (32 * 256);

        // prefetch all 4 neighbor fragments (8 x LDG.128, deep MLP)
        float4 v[8];
        #pragma unroll
        for (int g = 0; g < 4; g++) {
            const float* row = nb + (size_t)(warp + 8 * g) * 256;
            v[2 * g]     = *(const float4*)(row + lane * 4);
            v[2 * g + 1] = *(const float4*)(row + 128 + lane * 4);
        }

        float pm[10];
        #pragma unroll
        for (int j = 0; j < 10; j++) pm[j] = -3.0e38f;

        #pragma unroll
        for (int r = 0; r < 2; r++) {
            // pair of neighbors: gA = 2r (-> n = warp + 16r), gB = 2r+1 (-> n = warp+8+16r)
            unsigned long long accA[5], accB[5];
            #pragma unroll
            for (int jp = 0; jp < 5; jp++) { accA[jp] = 0ull; accB[jp] = 0ull; }

            #pragma unroll
            for (int half = 0; half < 2; half++) {
                float4 qa = v[4 * r + half];
                float4 qb = v[4 * r + 2 + half];
                float fa4[4] = {qa.x, qa.y, qa.z, qa.w};
                float fb4[4] = {qb.x, qb.y, qb.z, qb.w};
                #pragma unroll
                for (int c = 0; c < 4; c++) {
                    int i = half * 4 + c;
                    unsigned long long pa = pk2(fa4[c], fa4[c]);
                    unsigned long long pb = pk2(fb4[c], fb4[c]);
                    #pragma unroll
                    for (int jp = 0; jp < 5; jp++) {
                        fma2(accA[jp], pa, w1p[i][jp]);
                        fma2(accB[jp], pb, w1p[i][jp]);
                    }
                }
            }

            float fa[10], fb[10];
            #pragma unroll
            for (int jp = 0; jp < 5; jp++) {
                float2 t = upk2(accA[jp]); fa[2 * jp] = t.x; fa[2 * jp + 1] = t.y;
                float2 u = upk2(accB[jp]); fb[2 * jp] = u.x; fb[2 * jp + 1] = u.y;
            }
            // stage 16 on both vectors, then fold B into the upper warp half
            #pragma unroll
            for (int j = 0; j < 10; j++) fa[j] += __shfl_xor_sync(FULLMASK, fa[j], 16);
            #pragma unroll
            for (int j = 0; j < 10; j++) fb[j] += __shfl_xor_sync(FULLMASK, fb[j], 16);
            #pragma unroll
            for (int j = 0; j < 10; j++) {
                float cj = (lane < 16) ? fa[j] : fb[j];
                cj += __shfl_xor_sync(FULLMASK, cj, 8);
                cj += __shfl_xor_sync(FULLMASK, cj, 4);
                cj += __shfl_xor_sync(FULLMASK, cj, 2);
                cj += __shfl_xor_sync(FULLMASK, cj, 1);
                pm[j] = fmaxf(pm[j], cj);
            }
        }

        // lanes 0 / 16 hold max over the low-half / high-half neighbor sets
        if (lane == 0) {
            #pragma unroll
            for (int j = 0; j < 10; j++) smax[warp * 10 + j] = pm[j];
        } else if (lane == 16) {
            #pragma unroll
            for (int j = 0; j < 10; j++) smax[(warp + 8) * 10 + j] = pm[j];
        }
        __syncthreads();
        if (tid < 10) {
            float m = smax[tid];
            #pragma unroll
            for (int w = 1; w < 16; w++) m = fmaxf(m, smax[w * 10 + tid]);
            g_pooled[(size_t)b * 10 + tid] = m;
        }
        __syncthreads();
    }
}

// ---------------------------------------------------------------------------
// Kernel 2: from_self = self_vecs[ M x 256 ] @ Wt2[ 256 x 512 ] + bt2
// 128x128 block tile, BK=16, 256 threads, 8x8 per-thread tile as f32x2 pairs
// over M. Stores into out[:, 0:512] (row stride 1024).
// ---------------------------------------------------------------------------
__global__ void __launch_bounds__(256, 2)
k2_self_gemm(const float* __restrict__ A, const float* __restrict__ Bw,
             const float* __restrict__ bias, float* __restrict__ out, int M)
{
    __shared__ float As[16][132];
    __shared__ float Bs[16][132];
    const int tid = threadIdx.x;
    const int tx  = tid & 15;
    const int ty  = tid >> 4;
    const int m0  = blockIdx.y * 128;
    const int n0  = blockIdx.x * 128;

    unsigned long long acc[4][8];
    #pragma unroll
    for (int p = 0; p < 4; p++)
        #pragma unroll
        for (int j = 0; j < 8; j++) acc[p][j] = 0ull;

    for (int k0 = 0; k0 < 256; k0 += 16) {
        // A tile -> As[k][m] (transposed), guarded on M
        #pragma unroll
        for (int i = 0; i < 2; i++) {
            int idx = tid + i * 256;
            int row = idx >> 2;
            int kq  = (idx & 3) << 2;
            float4 va = make_float4(0.f, 0.f, 0.f, 0.f);
            if (m0 + row < M) va = *(const float4*)(A + (size_t)(m0 + row) * 256 + k0 + kq);
            As[kq + 0][row] = va.x; As[kq + 1][row] = va.y;
            As[kq + 2][row] = va.z; As[kq + 3][row] = va.w;
        }
        // B tile -> Bs[k][n]
        #pragma unroll
        for (int i = 0; i < 2; i++) {
            int idx = tid + i * 256;
            int kb  = idx >> 5;
            int nq  = (idx & 31) << 2;
            *(float4*)&Bs[kb][nq] = *(const float4*)(Bw + (size_t)(k0 + kb) * 512 + n0 + nq);
        }
        __syncthreads();

        #pragma unroll
        for (int kk = 0; kk < 16; kk++) {
            unsigned long long a0 = *(const unsigned long long*)&As[kk][ty * 4];
            unsigned long long a1 = *(const unsigned long long*)&As[kk][ty * 4 + 2];
            unsigned long long a2 = *(const unsigned long long*)&As[kk][64 + ty * 4];
            unsigned long long a3 = *(const unsigned long long*)&As[kk][64 + ty * 4 + 2];
            float4 b0 = *(const float4*)&Bs[kk][tx * 4];
            float4 b1 = *(const float4*)&Bs[kk][64 + tx * 4];
            unsigned long long pb[8] = {
                pk2(b0.x, b0.x), pk2(b0.y, b0.y), pk2(b0.z, b0.z), pk2(b0.w, b0.w),
                pk2(b1.x, b1.x), pk2(b1.y, b1.y), pk2(b1.z, b1.z), pk2(b1.w, b1.w)
            };
            #pragma unroll
            for (int j = 0; j < 8; j++) {
                fma2(acc[0][j], a0, pb[j]);
                fma2(acc[1][j], a1, pb[j]);
                fma2(acc[2][j], a2, pb[j]);
                fma2(acc[3][j], a3, pb[j]);
            }
        }
        __syncthreads();
    }

    float bv[8];
    #pragma unroll
    for (int j = 0; j < 4; j++) {
        bv[j]     = bias[n0 + tx * 4 + j];
        bv[4 + j] = bias[n0 + 64 + tx * 4 + j];
    }
    #pragma unroll
    for (int p = 0; p < 4; p++) {
        int rbase = m0 + ((p < 2) ? (ty * 4 + 2 * p) : (64 + ty * 4 + 2 * (p - 2)));
        float2 cl[8];
        #pragma unroll
        for (int j = 0; j < 8; j++) cl[j] = upk2(acc[p][j]);
        #pragma unroll
        for (int h = 0; h < 2; h++) {
            int row = rbase + h;
            if (row < M) {
                float4 o0 = make_float4((h ? cl[0].y : cl[0].x) + bv[0],
                                        (h ? cl[1].y : cl[1].x) + bv[1],
                                        (h ? cl[2].y : cl[2].x) + bv[2],
                                        (h ? cl[3].y : cl[3].x) + bv[3]);
                float4 o1 = make_float4((h ? cl[4].y : cl[4].x) + bv[4],
                                        (h ? cl[5].y : cl[5].x) + bv[5],
                                        (h ? cl[6].y : cl[6].x) + bv[6],
                                        (h ? cl[7].y : cl[7].x) + bv[7]);
                *(float4*)(out + (size_t)row * 1024 + n0 + tx * 4)      = o0;
                *(float4*)(out + (size_t)row * 1024 + n0 + 64 + tx * 4) = o1;
            }
        }
    }
}

// ---------------------------------------------------------------------------
// Kernel 3: from_neighs = relu(pooled + b1)[ M x 10 ] @ Wt1[ 10 x 512 ] + bt1
// 512 threads = 512 output columns; 128 rows per block. Wt1 column loaded to
// registers once per block. Stores into out[:, 512:1024].
// ---------------------------------------------------------------------------
__global__ void __launch_bounds__(512)
k3_neigh_out(const float* __restrict__ b1, const float* __restrict__ Wt1,
             const float* __restrict__ bt1, float* __restrict__ out, int B)
{
    __shared__ float ps[1280];  // 128 rows x 10
    const int o  = threadIdx.x;
    const int b0 = blockIdx.x * 128;
    const int nrows = min(128, B - b0);

    for (int idx = o; idx < nrows * 10; idx += 512) {
        int j = idx % 10;
        ps[idx] = fmaxf(g_pooled[(size_t)b0 * 10 + idx] + b1[j], 0.0f);
    }
    unsigned long long wtp[5];
    #pragma unroll
    for (int jp = 0; jp < 5; jp++)
        wtp[jp] = pk2(Wt1[(2 * jp) * 512 + o], Wt1[(2 * jp + 1) * 512 + o]);
    float bias = bt1[o];
    __syncthreads();

    for (int r = 0; r < nrows; r++) {
        const unsigned long long* pr = (const unsigned long long*)&ps[r * 10];
        unsigned long long s2 = 0ull;
        #pragma unroll
        for (int jp = 0; jp < 5; jp++) fma2(s2, pr[jp], wtp[jp]);
        float2 t = upk2(s2);
        out[(size_t)(b0 + r) * 1024 + 512 + o] = t.x + t.y + bias;
    }
}

// ---------------------------------------------------------------------------
extern "C" void kernel_launch(void* const* d_in, const int* in_sizes, int n_in,
                              void* d_out, int out_size)
{
    const float* self_vecs = (const float*)d_in[0];
    const float* neigh     = (const float*)d_in[1];
    const float* W1        = (const float*)d_in[2];
    const float* b1        = (const float*)d_in[3];
    const float* Wt1       = (const float*)d_in[4];
    const float* bt1       = (const float*)d_in[5];
    const float* Wt2       = (const float*)d_in[6];
    const float* bt2       = (const float*)d_in[7];
    float* out = (float*)d_out;

    const int B = in_sizes[0] / 256;

    k1_neigh_pool<<<592, 256>>>(neigh, W1, B);

    dim3 g2(4, (B + 127) / 128);
    k2_self_gemm<<<g2, 256>>>(self_vecs, Wt2, bt2, out, B);

    k3_neigh_out<<<(B + 127) / 128, 512>>>(b1, Wt1, bt1, out, B);
}

// round 2
// speedup vs baseline: 1.2233x; 1.2233x over previous
#include <cuda_runtime.h>
#include <cstdint>

#define FULLMASK 0xffffffffu

// scratch for pooled max (pre-bias, pre-relu): [B, 10], B = 20000
__device__ float g_pooled[20000 * 10];

__device__ __forceinline__ unsigned long long pk2(float x, float y) {
    unsigned long long r;
    asm("mov.b64 %0, {%1, %2};" : "=l"(r) : "f"(x), "f"(y));
    return r;
}
__device__ __forceinline__ float2 upk2(unsigned long long p) {
    float2 t;
    asm("mov.b64 {%0, %1}, %2;" : "=f"(t.x), "=f"(t.y) : "l"(p));
    return t;
}
__device__ __forceinline__ void fma2(unsigned long long& d, unsigned long long a, unsigned long long b) {
    asm("fma.rn.f32x2 %0, %1, %2, %0;" : "+l"(d) : "l"(a), "l"(b));
}
__device__ __forceinline__ uint32_t s2u(const void* p) {
    return (uint32_t)__cvta_generic_to_shared(p);
}
__device__ __forceinline__ void cp16(uint32_t dst, const float* src) {
    asm volatile("cp.async.cg.shared.global [%0], [%1], 16;" :: "r"(dst), "l"(src));
}

// ---------------------------------------------------------------------------
// Kernel 1 (v2): neighbor MLP (D=256 -> H=10) + max-pool over N=32 neighbors.
// Block = 256 threads, owns 1024 rows = 32 b's. cp.async double-buffered
// staging of [1024 rows x 16 floats] chunks (16 chunks over D=256).
// Thread t owns 4 full rows {t + 256*q}; h[4][10] accumulated in registers
// (f32x2 packed over H). Pooling = single warp shfl-max at the end.
// smem row pad = 20 floats (5 x 16B units; 5*lane mod 8 is a permutation ->
// conflict-free LDS.128).
// ---------------------------------------------------------------------------
#define K1_ROWS 1024
#define K1_RPAD 20
#define K1_BUFE (K1_ROWS * K1_RPAD)   // floats per buffer = 20480
#define K1_SMEM ((2560 + 2 * K1_BUFE) * 4)  // 174080 bytes

__global__ void __launch_bounds__(256, 1)
k1_neigh_pool(const float* __restrict__ neigh, const float* __restrict__ W1g, int B)
{
    extern __shared__ float sm[];
    float* w1s = sm;            // [256][10]
    float* buf = sm + 2560;     // [2][1024][20]

    const int tid  = threadIdx.x;
    const int lane = tid & 31;
    const int warp = tid >> 5;

    // stage W1 once (coalesced)
    for (int i = tid; i < 2560; i += 256) w1s[i] = W1g[i];

    const long long row0 = (long long)blockIdx.x * K1_ROWS;
    const long long rmax = (long long)B * 32;

    // issue loader: chunk c (16 floats of D) into buffer bi
    const int lrow = (tid >> 2);        // 0..63
    const int lseg = (tid & 3);         // 0..3

    {   // prologue: chunk 0 -> buffer 0
        const float* gbase = neigh + row0 * 256 + lseg * 4;
        #pragma unroll
        for (int p = 0; p < 16; p++) {
            int r = p * 64 + lrow;
            if (row0 + r < rmax)
                cp16(s2u(&buf[r * K1_RPAD + lseg * 4]), gbase + (long long)r * 256);
        }
        asm volatile("cp.async.commit_group;");
    }

    unsigned long long acc[4][5];
    #pragma unroll
    for (int q = 0; q < 4; q++)
        #pragma unroll
        for (int jp = 0; jp < 5; jp++) acc[q][jp] = 0ull;

    #pragma unroll 1
    for (int c = 0; c < 16; c++) {
        const int bi = c & 1;
        if (c < 15) {
            const int k0n = (c + 1) * 16;
            float* db = &buf[(1 - bi) * K1_BUFE];
            const float* gbase = neigh + row0 * 256 + k0n + lseg * 4;
            #pragma unroll
            for (int p = 0; p < 16; p++) {
                int r = p * 64 + lrow;
                if (row0 + r < rmax)
                    cp16(s2u(&db[r * K1_RPAD + lseg * 4]), gbase + (long long)r * 256);
            }
            asm volatile("cp.async.commit_group;");
            asm volatile("cp.async.wait_group 1;");
        } else {
            asm volatile("cp.async.wait_group 0;");
        }
        __syncthreads();

        // compute chunk c from buf[bi]
        const float* cb = &buf[bi * K1_BUFE];
        const int k0 = c * 16;
        #pragma unroll
        for (int j = 0; j < 4; j++) {
            const int d0 = k0 + j * 4;
            unsigned long long wpk[4][5];
            #pragma unroll
            for (int dd = 0; dd < 4; dd++)
                #pragma unroll
                for (int jp = 0; jp < 5; jp++)
                    wpk[dd][jp] = *(const unsigned long long*)&w1s[(d0 + dd) * 10 + 2 * jp];
            #pragma unroll
            for (int q = 0; q < 4; q++) {
                float4 x = *(const float4*)&cb[(tid + 256 * q) * K1_RPAD + j * 4];
                unsigned long long p0 = pk2(x.x, x.x);
                unsigned long long p1 = pk2(x.y, x.y);
                unsigned long long p2 = pk2(x.z, x.z);
                unsigned long long p3 = pk2(x.w, x.w);
                #pragma unroll
                for (int jp = 0; jp < 5; jp++) {
                    fma2(acc[q][jp], p0, wpk[0][jp]);
                    fma2(acc[q][jp], p1, wpk[1][jp]);
                    fma2(acc[q][jp], p2, wpk[2][jp]);
                    fma2(acc[q][jp], p3, wpk[3][jp]);
                }
            }
        }
        __syncthreads();
    }

    // epilogue: warp-max over the 32 lanes (= 32 rows of one b per (warp,q))
    #pragma unroll
    for (int q = 0; q < 4; q++) {
        float h[10];
        #pragma unroll
        for (int jp = 0; jp < 5; jp++) {
            float2 t = upk2(acc[q][jp]);
            h[2 * jp] = t.x; h[2 * jp + 1] = t.y;
        }
        #pragma unroll
        for (int j = 0; j < 10; j++) {
            #pragma unroll
            for (int off = 16; off > 0; off >>= 1)
                h[j] = fmaxf(h[j], __shfl_xor_sync(FULLMASK, h[j], off));
        }
        if (lane == 0) {
            long long b = (long long)blockIdx.x * 32 + warp + 8 * q;
            if (b < B) {
                #pragma unroll
                for (int j = 0; j < 10; j++) g_pooled[b * 10 + j] = h[j];
            }
        }
    }
}

// ---------------------------------------------------------------------------
// Kernel 2: from_self = self_vecs[ M x 256 ] @ Wt2[ 256 x 512 ] + bt2
// 128x128 block tile, BK=16, 256 threads, 8x8 per-thread tile as f32x2 pairs
// over M. Stores into out[:, 0:512] (row stride 1024).
// ---------------------------------------------------------------------------
__global__ void __launch_bounds__(256, 2)
k2_self_gemm(const float* __restrict__ A, const float* __restrict__ Bw,
             const float* __restrict__ bias, float* __restrict__ out, int M)
{
    __shared__ float As[16][132];
    __shared__ float Bs[16][132];
    const int tid = threadIdx.x;
    const int tx  = tid & 15;
    const int ty  = tid >> 4;
    const int m0  = blockIdx.y * 128;
    const int n0  = blockIdx.x * 128;

    unsigned long long acc[4][8];
    #pragma unroll
    for (int p = 0; p < 4; p++)
        #pragma unroll
        for (int j = 0; j < 8; j++) acc[p][j] = 0ull;

    for (int k0 = 0; k0 < 256; k0 += 16) {
        #pragma unroll
        for (int i = 0; i < 2; i++) {
            int idx = tid + i * 256;
            int row = idx >> 2;
            int kq  = (idx & 3) << 2;
            float4 va = make_float4(0.f, 0.f, 0.f, 0.f);
            if (m0 + row < M) va = *(const float4*)(A + (size_t)(m0 + row) * 256 + k0 + kq);
            As[kq + 0][row] = va.x; As[kq + 1][row] = va.y;
            As[kq + 2][row] = va.z; As[kq + 3][row] = va.w;
        }
        #pragma unroll
        for (int i = 0; i < 2; i++) {
            int idx = tid + i * 256;
            int kb  = idx >> 5;
            int nq  = (idx & 31) << 2;
            *(float4*)&Bs[kb][nq] = *(const float4*)(Bw + (size_t)(k0 + kb) * 512 + n0 + nq);
        }
        __syncthreads();

        #pragma unroll
        for (int kk = 0; kk < 16; kk++) {
            unsigned long long a0 = *(const unsigned long long*)&As[kk][ty * 4];
            unsigned long long a1 = *(const unsigned long long*)&As[kk][ty * 4 + 2];
            unsigned long long a2 = *(const unsigned long long*)&As[kk][64 + ty * 4];
            unsigned long long a3 = *(const unsigned long long*)&As[kk][64 + ty * 4 + 2];
            float4 b0 = *(const float4*)&Bs[kk][tx * 4];
            float4 b1 = *(const float4*)&Bs[kk][64 + tx * 4];
            unsigned long long pb[8] = {
                pk2(b0.x, b0.x), pk2(b0.y, b0.y), pk2(b0.z, b0.z), pk2(b0.w, b0.w),
                pk2(b1.x, b1.x), pk2(b1.y, b1.y), pk2(b1.z, b1.z), pk2(b1.w, b1.w)
            };
            #pragma unroll
            for (int j = 0; j < 8; j++) {
                fma2(acc[0][j], a0, pb[j]);
                fma2(acc[1][j], a1, pb[j]);
                fma2(acc[2][j], a2, pb[j]);
                fma2(acc[3][j], a3, pb[j]);
            }
        }
        __syncthreads();
    }

    float bv[8];
    #pragma unroll
    for (int j = 0; j < 4; j++) {
        bv[j]     = bias[n0 + tx * 4 + j];
        bv[4 + j] = bias[n0 + 64 + tx * 4 + j];
    }
    #pragma unroll
    for (int p = 0; p < 4; p++) {
        int rbase = m0 + ((p < 2) ? (ty * 4 + 2 * p) : (64 + ty * 4 + 2 * (p - 2)));
        float2 cl[8];
        #pragma unroll
        for (int j = 0; j < 8; j++) cl[j] = upk2(acc[p][j]);
        #pragma unroll
        for (int h = 0; h < 2; h++) {
            int row = rbase + h;
            if (row < M) {
                float4 o0 = make_float4((h ? cl[0].y : cl[0].x) + bv[0],
                                        (h ? cl[1].y : cl[1].x) + bv[1],
                                        (h ? cl[2].y : cl[2].x) + bv[2],
                                        (h ? cl[3].y : cl[3].x) + bv[3]);
                float4 o1 = make_float4((h ? cl[4].y : cl[4].x) + bv[4],
                                        (h ? cl[5].y : cl[5].x) + bv[5],
                                        (h ? cl[6].y : cl[6].x) + bv[6],
                                        (h ? cl[7].y : cl[7].x) + bv[7]);
                *(float4*)(out + (size_t)row * 1024 + n0 + tx * 4)      = o0;
                *(float4*)(out + (size_t)row * 1024 + n0 + 64 + tx * 4) = o1;
            }
        }
    }
}

// ---------------------------------------------------------------------------
// Kernel 3: from_neighs = relu(pooled + b1)[ M x 10 ] @ Wt1[ 10 x 512 ] + bt1
// ---------------------------------------------------------------------------
__global__ void __launch_bounds__(512)
k3_neigh_out(const float* __restrict__ b1, const float* __restrict__ Wt1,
             const float* __restrict__ bt1, float* __restrict__ out, int B)
{
    __shared__ float ps[1280];  // 128 rows x 10
    const int o  = threadIdx.x;
    const int b0 = blockIdx.x * 128;
    const int nrows = min(128, B - b0);

    for (int idx = o; idx < nrows * 10; idx += 512) {
        int j = idx % 10;
        ps[idx] = fmaxf(g_pooled[(size_t)b0 * 10 + idx] + b1[j], 0.0f);
    }
    unsigned long long wtp[5];
    #pragma unroll
    for (int jp = 0; jp < 5; jp++)
        wtp[jp] = pk2(Wt1[(2 * jp) * 512 + o], Wt1[(2 * jp + 1) * 512 + o]);
    float bias = bt1[o];
    __syncthreads();

    for (int r = 0; r < nrows; r++) {
        const unsigned long long* pr = (const unsigned long long*)&ps[r * 10];
        unsigned long long s2 = 0ull;
        #pragma unroll
        for (int jp = 0; jp < 5; jp++) fma2(s2, pr[jp], wtp[jp]);
        float2 t = upk2(s2);
        out[(size_t)(b0 + r) * 1024 + 512 + o] = t.x + t.y + bias;
    }
}

// ---------------------------------------------------------------------------
extern "C" void kernel_launch(void* const* d_in, const int* in_sizes, int n_in,
                              void* d_out, int out_size)
{
    const float* self_vecs = (const float*)d_in[0];
    const float* neigh     = (const float*)d_in[1];
    const float* W1        = (const float*)d_in[2];
    const float* b1        = (const float*)d_in[3];
    const float* Wt1       = (const float*)d_in[4];
    const float* bt1       = (const float*)d_in[5];
    const float* Wt2       = (const float*)d_in[6];
    const float* bt2       = (const float*)d_in[7];
    float* out = (float*)d_out;

    const int B = in_sizes[0] / 256;

    cudaFuncSetAttribute(k1_neigh_pool, cudaFuncAttributeMaxDynamicSharedMemorySize, K1_SMEM);

    k1_neigh_pool<<<(B + 31) / 32, 256, K1_SMEM>>>(neigh, W1, B);

    dim3 g2(4, (B + 127) / 128);
    k2_self_gemm<<<g2, 256>>>(self_vecs, Wt2, bt2, out, B);

    k3_neigh_out<<<(B + 127) / 128, 512>>>(b1, Wt1, bt1, out, B);
}

// round 3
// speedup vs baseline: 1.2282x; 1.0040x over previous
#include <cuda_runtime.h>
#include <cstdint>

#define FULLMASK 0xffffffffu

// scratch for pooled max (pre-bias, pre-relu): [B, 10], B = 20000
__device__ float g_pooled[20000 * 10];

__device__ __forceinline__ unsigned long long pk2(float x, float y) {
    unsigned long long r;
    asm("mov.b64 %0, {%1, %2};" : "=l"(r) : "f"(x), "f"(y));
    return r;
}
__device__ __forceinline__ float2 upk2(unsigned long long p) {
    float2 t;
    asm("mov.b64 {%0, %1}, %2;" : "=f"(t.x), "=f"(t.y) : "l"(p));
    return t;
}
__device__ __forceinline__ void fma2(unsigned long long& d, unsigned long long a, unsigned long long b) {
    asm("fma.rn.f32x2 %0, %1, %2, %0;" : "+l"(d) : "l"(a), "l"(b));
}
__device__ __forceinline__ uint32_t s2u(const void* p) {
    return (uint32_t)__cvta_generic_to_shared(p);
}
__device__ __forceinline__ void cp16(uint32_t dst, const float* src) {
    asm volatile("cp.async.cg.shared.global [%0], [%1], 16;" :: "r"(dst), "l"(src));
}

// ---------------------------------------------------------------------------
// Kernel 1 (v2): neighbor MLP (D=256 -> H=10) + max-pool over N=32 neighbors.
// Block = 256 threads, owns 1024 rows = 32 b's. cp.async double-buffered
// staging of [1024 rows x 16 floats] chunks (16 chunks over D=256).
// Thread t owns 4 full rows {t + 256*q}; h[4][10] accumulated in registers
// (f32x2 packed over H). Pooling = single warp shfl-max at the end.
// smem row pad = 20 floats (5 x 16B units; 5*lane mod 8 is a permutation ->
// conflict-free LDS.128).
// ---------------------------------------------------------------------------
#define K1_ROWS 1024
#define K1_RPAD 20
#define K1_BUFE (K1_ROWS * K1_RPAD)   // floats per buffer = 20480
#define K1_SMEM ((2560 + 2 * K1_BUFE) * 4)  // 174080 bytes

__global__ void __launch_bounds__(256, 1)
k1_neigh_pool(const float* __restrict__ neigh, const float* __restrict__ W1g, int B)
{
    extern __shared__ float sm[];
    float* w1s = sm;            // [256][10]
    float* buf = sm + 2560;     // [2][1024][20]

    const int tid  = threadIdx.x;
    const int lane = tid & 31;
    const int warp = tid >> 5;

    // stage W1 once (coalesced)
    for (int i = tid; i < 2560; i += 256) w1s[i] = W1g[i];

    const long long row0 = (long long)blockIdx.x * K1_ROWS;
    const long long rmax = (long long)B * 32;

    // issue loader: chunk c (16 floats of D) into buffer bi
    const int lrow = (tid >> 2);        // 0..63
    const int lseg = (tid & 3);         // 0..3

    {   // prologue: chunk 0 -> buffer 0
        const float* gbase = neigh + row0 * 256 + lseg * 4;
        #pragma unroll
        for (int p = 0; p < 16; p++) {
            int r = p * 64 + lrow;
            if (row0 + r < rmax)
                cp16(s2u(&buf[r * K1_RPAD + lseg * 4]), gbase + (long long)r * 256);
        }
        asm volatile("cp.async.commit_group;");
    }

    unsigned long long acc[4][5];
    #pragma unroll
    for (int q = 0; q < 4; q++)
        #pragma unroll
        for (int jp = 0; jp < 5; jp++) acc[q][jp] = 0ull;

    #pragma unroll 1
    for (int c = 0; c < 16; c++) {
        const int bi = c & 1;
        if (c < 15) {
            const int k0n = (c + 1) * 16;
            float* db = &buf[(1 - bi) * K1_BUFE];
            const float* gbase = neigh + row0 * 256 + k0n + lseg * 4;
            #pragma unroll
            for (int p = 0; p < 16; p++) {
                int r = p * 64 + lrow;
                if (row0 + r < rmax)
                    cp16(s2u(&db[r * K1_RPAD + lseg * 4]), gbase + (long long)r * 256);
            }
            asm volatile("cp.async.commit_group;");
            asm volatile("cp.async.wait_group 1;");
        } else {
            asm volatile("cp.async.wait_group 0;");
        }
        __syncthreads();

        // compute chunk c from buf[bi]
        const float* cb = &buf[bi * K1_BUFE];
        const int k0 = c * 16;
        #pragma unroll
        for (int j = 0; j < 4; j++) {
            const int d0 = k0 + j * 4;
            unsigned long long wpk[4][5];
            #pragma unroll
            for (int dd = 0; dd < 4; dd++)
                #pragma unroll
                for (int jp = 0; jp < 5; jp++)
                    wpk[dd][jp] = *(const unsigned long long*)&w1s[(d0 + dd) * 10 + 2 * jp];
            #pragma unroll
            for (int q = 0; q < 4; q++) {
                float4 x = *(const float4*)&cb[(tid + 256 * q) * K1_RPAD + j * 4];
                unsigned long long p0 = pk2(x.x, x.x);
                unsigned long long p1 = pk2(x.y, x.y);
                unsigned long long p2 = pk2(x.z, x.z);
                unsigned long long p3 = pk2(x.w, x.w);
                #pragma unroll
                for (int jp = 0; jp < 5; jp++) {
                    fma2(acc[q][jp], p0, wpk[0][jp]);
                    fma2(acc[q][jp], p1, wpk[1][jp]);
                    fma2(acc[q][jp], p2, wpk[2][jp]);
                    fma2(acc[q][jp], p3, wpk[3][jp]);
                }
            }
        }
        __syncthreads();
    }

    // epilogue: warp-max over the 32 lanes (= 32 rows of one b per (warp,q))
    #pragma unroll
    for (int q = 0; q < 4; q++) {
        float h[10];
        #pragma unroll
        for (int jp = 0; jp < 5; jp++) {
            float2 t = upk2(acc[q][jp]);
            h[2 * jp] = t.x; h[2 * jp + 1] = t.y;
        }
        #pragma unroll
        for (int j = 0; j < 10; j++) {
            #pragma unroll
            for (int off = 16; off > 0; off >>= 1)
                h[j] = fmaxf(h[j], __shfl_xor_sync(FULLMASK, h[j], off));
        }
        if (lane == 0) {
            long long b = (long long)blockIdx.x * 32 + warp + 8 * q;
            if (b < B) {
                #pragma unroll
                for (int j = 0; j < 10; j++) g_pooled[b * 10 + j] = h[j];
            }
        }
    }
}

// ---------------------------------------------------------------------------
// Kernel 2: from_self = self_vecs[ M x 256 ] @ Wt2[ 256 x 512 ] + bt2
// 128x128 block tile, BK=16, 256 threads, 8x8 per-thread tile as f32x2 pairs
// over M. Stores into out[:, 0:512] (row stride 1024).
// ---------------------------------------------------------------------------
__global__ void __launch_bounds__(256, 2)
k2_self_gemm(const float* __restrict__ A, const float* __restrict__ Bw,
             const float* __restrict__ bias, float* __restrict__ out, int M)
{
    __shared__ float As[16][132];
    __shared__ float Bs[16][132];
    const int tid = threadIdx.x;
    const int tx  = tid & 15;
    const int ty  = tid >> 4;
    const int m0  = blockIdx.y * 128;
    const int n0  = blockIdx.x * 128;

    unsigned long long acc[4][8];
    #pragma unroll
    for (int p = 0; p < 4; p++)
        #pragma unroll
        for (int j = 0; j < 8; j++) acc[p][j] = 0ull;

    for (int k0 = 0; k0 < 256; k0 += 16) {
        #pragma unroll
        for (int i = 0; i < 2; i++) {
            int idx = tid + i * 256;
            int row = idx >> 2;
            int kq  = (idx & 3) << 2;
            float4 va = make_float4(0.f, 0.f, 0.f, 0.f);
            if (m0 + row < M) va = *(const float4*)(A + (size_t)(m0 + row) * 256 + k0 + kq);
            As[kq + 0][row] = va.x; As[kq + 1][row] = va.y;
            As[kq + 2][row] = va.z; As[kq + 3][row] = va.w;
        }
        #pragma unroll
        for (int i = 0; i < 2; i++) {
            int idx = tid + i * 256;
            int kb  = idx >> 5;
            int nq  = (idx & 31) << 2;
            *(float4*)&Bs[kb][nq] = *(const float4*)(Bw + (size_t)(k0 + kb) * 512 + n0 + nq);
        }
        __syncthreads();

        #pragma unroll
        for (int kk = 0; kk < 16; kk++) {
            unsigned long long a0 = *(const unsigned long long*)&As[kk][ty * 4];
            unsigned long long a1 = *(const unsigned long long*)&As[kk][ty * 4 + 2];
            unsigned long long a2 = *(const unsigned long long*)&As[kk][64 + ty * 4];
            unsigned long long a3 = *(const unsigned long long*)&As[kk][64 + ty * 4 + 2];
            float4 b0 = *(const float4*)&Bs[kk][tx * 4];
            float4 b1 = *(const float4*)&Bs[kk][64 + tx * 4];
            unsigned long long pb[8] = {
                pk2(b0.x, b0.x), pk2(b0.y, b0.y), pk2(b0.z, b0.z), pk2(b0.w, b0.w),
                pk2(b1.x, b1.x), pk2(b1.y, b1.y), pk2(b1.z, b1.z), pk2(b1.w, b1.w)
            };
            #pragma unroll
            for (int j = 0; j < 8; j++) {
                fma2(acc[0][j], a0, pb[j]);
                fma2(acc[1][j], a1, pb[j]);
                fma2(acc[2][j], a2, pb[j]);
                fma2(acc[3][j], a3, pb[j]);
            }
        }
        __syncthreads();
    }

    float bv[8];
    #pragma unroll
    for (int j = 0; j < 4; j++) {
        bv[j]     = bias[n0 + tx * 4 + j];
        bv[4 + j] = bias[n0 + 64 + tx * 4 + j];
    }
    #pragma unroll
    for (int p = 0; p < 4; p++) {
        int rbase = m0 + ((p < 2) ? (ty * 4 + 2 * p) : (64 + ty * 4 + 2 * (p - 2)));
        float2 cl[8];
        #pragma unroll
        for (int j = 0; j < 8; j++) cl[j] = upk2(acc[p][j]);
        #pragma unroll
        for (int h = 0; h < 2; h++) {
            int row = rbase + h;
            if (row < M) {
                float4 o0 = make_float4((h ? cl[0].y : cl[0].x) + bv[0],
                                        (h ? cl[1].y : cl[1].x) + bv[1],
                                        (h ? cl[2].y : cl[2].x) + bv[2],
                                        (h ? cl[3].y : cl[3].x) + bv[3]);
                float4 o1 = make_float4((h ? cl[4].y : cl[4].x) + bv[4],
                                        (h ? cl[5].y : cl[5].x) + bv[5],
                                        (h ? cl[6].y : cl[6].x) + bv[6],
                                        (h ? cl[7].y : cl[7].x) + bv[7]);
                *(float4*)(out + (size_t)row * 1024 + n0 + tx * 4)      = o0;
                *(float4*)(out + (size_t)row * 1024 + n0 + 64 + tx * 4) = o1;
            }
        }
    }
}

// ---------------------------------------------------------------------------
// Kernel 3: from_neighs = relu(pooled + b1)[ M x 10 ] @ Wt1[ 10 x 512 ] + bt1
// ---------------------------------------------------------------------------
__global__ void __launch_bounds__(512)
k3_neigh_out(const float* __restrict__ b1, const float* __restrict__ Wt1,
             const float* __restrict__ bt1, float* __restrict__ out, int B)
{
    __shared__ float ps[1280];  // 128 rows x 10
    const int o  = threadIdx.x;
    const int b0 = blockIdx.x * 128;
    const int nrows = min(128, B - b0);

    for (int idx = o; idx < nrows * 10; idx += 512) {
        int j = idx % 10;
        ps[idx] = fmaxf(g_pooled[(size_t)b0 * 10 + idx] + b1[j], 0.0f);
    }
    unsigned long long wtp[5];
    #pragma unroll
    for (int jp = 0; jp < 5; jp++)
        wtp[jp] = pk2(Wt1[(2 * jp) * 512 + o], Wt1[(2 * jp + 1) * 512 + o]);
    float bias = bt1[o];
    __syncthreads();

    for (int r = 0; r < nrows; r++) {
        const unsigned long long* pr = (const unsigned long long*)&ps[r * 10];
        unsigned long long s2 = 0ull;
        #pragma unroll
        for (int jp = 0; jp < 5; jp++) fma2(s2, pr[jp], wtp[jp]);
        float2 t = upk2(s2);
        out[(size_t)(b0 + r) * 1024 + 512 + o] = t.x + t.y + bias;
    }
}

// ---------------------------------------------------------------------------
extern "C" void kernel_launch(void* const* d_in, const int* in_sizes, int n_in,
                              void* d_out, int out_size)
{
    const float* self_vecs = (const float*)d_in[0];
    const float* neigh     = (const float*)d_in[1];
    const float* W1        = (const float*)d_in[2];
    const float* b1        = (const float*)d_in[3];
    const float* Wt1       = (const float*)d_in[4];
    const float* bt1       = (const float*)d_in[5];
    const float* Wt2       = (const float*)d_in[6];
    const float* bt2       = (const float*)d_in[7];
    float* out = (float*)d_out;

    const int B = in_sizes[0] / 256;

    cudaFuncSetAttribute(k1_neigh_pool, cudaFuncAttributeMaxDynamicSharedMemorySize, K1_SMEM);

    k1_neigh_pool<<<(B + 31) / 32, 256, K1_SMEM>>>(neigh, W1, B);

    dim3 g2(4, (B + 127) / 128);
    k2_self_gemm<<<g2, 256>>>(self_vecs, Wt2, bt2, out, B);

    k3_neigh_out<<<(B + 127) / 128, 512>>>(b1, Wt1, bt1, out, B);
}

// round 4
// speedup vs baseline: 1.4032x; 1.1424x over previous
#include <cuda_runtime.h>
#include <cuda.h>
#include <cstdint>

typedef unsigned long long ull;
#define FULLMASK 0xffffffffu

__device__ float g_pooled[20000 * 10];

__device__ __forceinline__ ull pk2(float x, float y) {
    ull r; asm("mov.b64 %0, {%1, %2};" : "=l"(r) : "f"(x), "f"(y)); return r;
}
__device__ __forceinline__ float2 upk2(ull p) {
    float2 t; asm("mov.b64 {%0, %1}, %2;" : "=f"(t.x), "=f"(t.y) : "l"(p)); return t;
}
__device__ __forceinline__ void fma2(ull& d, ull a, ull b) {
    asm("fma.rn.f32x2 %0, %1, %2, %0;" : "+l"(d) : "l"(a), "l"(b));
}
__device__ __forceinline__ void add2(ull& d, ull a) {
    asm("add.rn.f32x2 %0, %0, %1;" : "+l"(d) : "l"(a));
}

// ---- k1 smem layout (bytes) ----
#define BUFB   32768
#define W1OFF  (4 * BUFB)           // 131072
#define SCROFF (W1OFF + 2560 * 4)   // 141312 : 3*64*4*5 ull = 30720 B
#define MBOFF  (SCROFF + 30720)     // 172032
#define K1SMEM (MBOFF + 64)

__device__ __forceinline__ void mbar_wait(uint32_t mb, uint32_t ph) {
    uint32_t done;
    asm volatile("{\n\t.reg .pred p;\n\t"
        "mbarrier.try_wait.parity.acquire.cta.shared::cta.b64 p, [%1], %2;\n\t"
        "selp.b32 %0, 1, 0, p;\n\t}" : "=r"(done) : "r"(mb), "r"(ph) : "memory");
    while (!done) {
        asm volatile("{\n\t.reg .pred p;\n\t"
            "mbarrier.try_wait.parity.acquire.cta.shared::cta.b64 p, [%1], %2, 10000000;\n\t"
            "selp.b32 %0, 1, 0, p;\n\t}" : "=r"(done) : "r"(mb), "r"(ph) : "memory");
    }
}

// ---------------------------------------------------------------------------
// k1 (TMA): neighbor MLP (D=256 -> H=10) + maxpool over 32 neighbors.
// Tile = 256 rows x 32 cols fp32 (SW128), 8 chunks per 256-row tile over D.
// 4-buffer TMA pipeline. Thread: d-slice ds = t>>6 (8 d's), rows (t&63)+64q.
// ---------------------------------------------------------------------------
__global__ void __launch_bounds__(256, 1)
k1_neigh_pool(const __grid_constant__ CUtensorMap tmap,
              const float* __restrict__ W1, int B)
{
    extern __shared__ char sm[];
    float* w1s = (float*)(sm + W1OFF);
    ull* scr = (ull*)(sm + SCROFF);
    const uint32_t smb = (uint32_t)__cvta_generic_to_shared(sm);
    const uint32_t mb0 = smb + MBOFF;
    const int t = threadIdx.x;
    const int lane = t & 31, warp = t >> 5;
    const int ds = t >> 6, rbase = t & 63;
    const int G = gridDim.x, bid = blockIdx.x;

    for (int i = t; i < 2560; i += 256) w1s[i] = W1[i];
    if (t == 0) {
        #pragma unroll
        for (int s = 0; s < 4; s++)
            asm volatile("mbarrier.init.shared.b64 [%0], 1;" :: "r"(mb0 + 8 * s) : "memory");
        asm volatile("fence.proxy.async.shared::cta;" ::: "memory");
    }
    __syncthreads();

    const int NT = (B * 32 + 255) >> 8;
    const int ntiles = (bid < NT) ? (NT - bid + G - 1) / G : 0;
    const int totc = ntiles * 8;

    auto issue = [&](int i) {
        int gt = bid + G * (i >> 3);
        uint32_t dst = smb + (i & 3) * BUFB;
        uint32_t mb = mb0 + 8 * (i & 3);
        asm volatile("mbarrier.arrive.expect_tx.shared.b64 _, [%0], %1;"
                     :: "r"(mb), "r"(32768u) : "memory");
        int x = (i & 7) * 32, y = gt * 256;
        asm volatile("cp.async.bulk.tensor.2d.shared::cta.global.tile.mbarrier::complete_tx::bytes"
                     " [%0], [%1, {%2, %3}], [%4];"
                     :: "r"(dst), "l"(&tmap), "r"(x), "r"(y), "r"(mb) : "memory");
    };
    if (t == 0) { int pre = totc < 3 ? totc : 3; for (int i = 0; i < pre; i++) issue(i); }

    ull acc[4][5];
    #pragma unroll
    for (int q = 0; q < 4; q++)
        #pragma unroll
        for (int jp = 0; jp < 5; jp++) acc[q][jp] = 0ull;

    #pragma unroll 1
    for (int i = 0; i < totc; i++) {
        if (t == 0 && i + 3 < totc) issue(i + 3);
        mbar_wait(mb0 + 8 * (i & 3), (uint32_t)((i >> 2) & 1));

        const char* bb = sm + (i & 3) * BUFB;
        const int c = i & 7;
        const int d0 = c * 32 + ds * 8;
        #pragma unroll
        for (int g = 0; g < 2; g++) {
            const int dg = d0 + g * 4;
            ull wpk[4][5];
            #pragma unroll
            for (int dd = 0; dd < 4; dd++)
                #pragma unroll
                for (int jp = 0; jp < 5; jp++)
                    wpk[dd][jp] = *(const ull*)&w1s[(dg + dd) * 10 + 2 * jp];
            #pragma unroll
            for (int q = 0; q < 4; q++) {
                int r = rbase + 64 * q;
                int off = r * 128 + (2 * ds + g) * 16;
                int phys = off ^ ((r & 7) << 4);
                float4 x = *(const float4*)(bb + phys);
                ull p0 = pk2(x.x, x.x), p1 = pk2(x.y, x.y);
                ull p2 = pk2(x.z, x.z), p3 = pk2(x.w, x.w);
                #pragma unroll
                for (int jp = 0; jp < 5; jp++) {
                    fma2(acc[q][jp], p0, wpk[0][jp]);
                    fma2(acc[q][jp], p1, wpk[1][jp]);
                    fma2(acc[q][jp], p2, wpk[2][jp]);
                    fma2(acc[q][jp], p3, wpk[3][jp]);
                }
            }
        }

        if (c == 7) {
            const int gt = bid + G * (i >> 3);
            if (ds) {
                ull* dp = scr + (((ds - 1) * 64 + rbase) * 4) * 5;
                #pragma unroll
                for (int q = 0; q < 4; q++)
                    #pragma unroll
                    for (int jp = 0; jp < 5; jp++) dp[q * 5 + jp] = acc[q][jp];
            }
            __syncthreads();
            if (ds == 0) {
                #pragma unroll
                for (int s = 0; s < 3; s++) {
                    const ull* sp = scr + ((s * 64 + rbase) * 4) * 5;
                    #pragma unroll
                    for (int q = 0; q < 4; q++)
                        #pragma unroll
                        for (int jp = 0; jp < 5; jp++) add2(acc[q][jp], sp[q * 5 + jp]);
                }
                #pragma unroll
                for (int q = 0; q < 4; q++) {
                    float h[10];
                    #pragma unroll
                    for (int jp = 0; jp < 5; jp++) {
                        float2 v = upk2(acc[q][jp]);
                        h[2 * jp] = v.x; h[2 * jp + 1] = v.y;
                    }
                    #pragma unroll
                    for (int j = 0; j < 10; j++)
                        #pragma unroll
                        for (int o = 16; o > 0; o >>= 1)
                            h[j] = fmaxf(h[j], __shfl_xor_sync(FULLMASK, h[j], o));
                    if (lane == 0) {
                        int b = gt * 8 + 2 * q + warp;
                        if (b < B) {
                            #pragma unroll
                            for (int j = 0; j < 10; j++)
                                g_pooled[(size_t)b * 10 + j] = h[j];
                        }
                    }
                }
            }
            #pragma unroll
            for (int q = 0; q < 4; q++)
                #pragma unroll
                for (int jp = 0; jp < 5; jp++) acc[q][jp] = 0ull;
        }
        __syncthreads();
    }
}

// ---------------------------------------------------------------------------
// k2: from_self = self_vecs[M x 256] @ Wt2[256 x 512] + bt2 (unchanged)
// ---------------------------------------------------------------------------
__global__ void __launch_bounds__(256, 2)
k2_self_gemm(const float* __restrict__ A, const float* __restrict__ Bw,
             const float* __restrict__ bias, float* __restrict__ out, int M)
{
    __shared__ float As[16][132];
    __shared__ float Bs[16][132];
    const int tid = threadIdx.x;
    const int tx = tid & 15, ty = tid >> 4;
    const int m0 = blockIdx.y * 128, n0 = blockIdx.x * 128;

    ull acc[4][8];
    #pragma unroll
    for (int p = 0; p < 4; p++)
        #pragma unroll
        for (int j = 0; j < 8; j++) acc[p][j] = 0ull;

    for (int k0 = 0; k0 < 256; k0 += 16) {
        #pragma unroll
        for (int i = 0; i < 2; i++) {
            int idx = tid + i * 256;
            int row = idx >> 2, kq = (idx & 3) << 2;
            float4 va = make_float4(0.f, 0.f, 0.f, 0.f);
            if (m0 + row < M) va = *(const float4*)(A + (size_t)(m0 + row) * 256 + k0 + kq);
            As[kq + 0][row] = va.x; As[kq + 1][row] = va.y;
            As[kq + 2][row] = va.z; As[kq + 3][row] = va.w;
        }
        #pragma unroll
        for (int i = 0; i < 2; i++) {
            int idx = tid + i * 256;
            int kb = idx >> 5, nq = (idx & 31) << 2;
            *(float4*)&Bs[kb][nq] = *(const float4*)(Bw + (size_t)(k0 + kb) * 512 + n0 + nq);
        }
        __syncthreads();
        #pragma unroll
        for (int kk = 0; kk < 16; kk++) {
            ull a0 = *(const ull*)&As[kk][ty * 4];
            ull a1 = *(const ull*)&As[kk][ty * 4 + 2];
            ull a2 = *(const ull*)&As[kk][64 + ty * 4];
            ull a3 = *(const ull*)&As[kk][64 + ty * 4 + 2];
            float4 b0 = *(const float4*)&Bs[kk][tx * 4];
            float4 b1 = *(const float4*)&Bs[kk][64 + tx * 4];
            ull pb[8] = {pk2(b0.x, b0.x), pk2(b0.y, b0.y), pk2(b0.z, b0.z), pk2(b0.w, b0.w),
                         pk2(b1.x, b1.x), pk2(b1.y, b1.y), pk2(b1.z, b1.z), pk2(b1.w, b1.w)};
            #pragma unroll
            for (int j = 0; j < 8; j++) {
                fma2(acc[0][j], a0, pb[j]); fma2(acc[1][j], a1, pb[j]);
                fma2(acc[2][j], a2, pb[j]); fma2(acc[3][j], a3, pb[j]);
            }
        }
        __syncthreads();
    }

    float bv[8];
    #pragma unroll
    for (int j = 0; j < 4; j++) {
        bv[j] = bias[n0 + tx * 4 + j];
        bv[4 + j] = bias[n0 + 64 + tx * 4 + j];
    }
    #pragma unroll
    for (int p = 0; p < 4; p++) {
        int rbase = m0 + ((p < 2) ? (ty * 4 + 2 * p) : (64 + ty * 4 + 2 * (p - 2)));
        float2 cl[8];
        #pragma unroll
        for (int j = 0; j < 8; j++) cl[j] = upk2(acc[p][j]);
        #pragma unroll
        for (int h = 0; h < 2; h++) {
            int row = rbase + h;
            if (row < M) {
                float4 o0 = make_float4((h ? cl[0].y : cl[0].x) + bv[0], (h ? cl[1].y : cl[1].x) + bv[1],
                                        (h ? cl[2].y : cl[2].x) + bv[2], (h ? cl[3].y : cl[3].x) + bv[3]);
                float4 o1 = make_float4((h ? cl[4].y : cl[4].x) + bv[4], (h ? cl[5].y : cl[5].x) + bv[5],
                                        (h ? cl[6].y : cl[6].x) + bv[6], (h ? cl[7].y : cl[7].x) + bv[7]);
                *(float4*)(out + (size_t)row * 1024 + n0 + tx * 4) = o0;
                *(float4*)(out + (size_t)row * 1024 + n0 + 64 + tx * 4) = o1;
            }
        }
    }
}

// ---------------------------------------------------------------------------
// k3: from_neighs = relu(pooled + b1) @ Wt1 + bt1 (unchanged)
// ---------------------------------------------------------------------------
__global__ void __launch_bounds__(512)
k3_neigh_out(const float* __restrict__ b1, const float* __restrict__ Wt1,
             const float* __restrict__ bt1, float* __restrict__ out, int B)
{
    __shared__ float ps[1280];
    const int o = threadIdx.x;
    const int b0 = blockIdx.x * 128;
    const int nrows = min(128, B - b0);

    for (int idx = o; idx < nrows * 10; idx += 512) {
        int j = idx % 10;
        ps[idx] = fmaxf(g_pooled[(size_t)b0 * 10 + idx] + b1[j], 0.0f);
    }
    ull wtp[5];
    #pragma unroll
    for (int jp = 0; jp < 5; jp++)
        wtp[jp] = pk2(Wt1[(2 * jp) * 512 + o], Wt1[(2 * jp + 1) * 512 + o]);
    float bias = bt1[o];
    __syncthreads();

    for (int r = 0; r < nrows; r++) {
        const ull* pr = (const ull*)&ps[r * 10];
        ull s2 = 0ull;
        #pragma unroll
        for (int jp = 0; jp < 5; jp++) fma2(s2, pr[jp], wtp[jp]);
        float2 t = upk2(s2);
        out[(size_t)(b0 + r) * 1024 + 512 + o] = t.x + t.y + bias;
    }
}

// ---------------------------------------------------------------------------
typedef CUresult (*EncodeFn)(CUtensorMap*, CUtensorMapDataType, cuuint32_t, void*,
                             const cuuint64_t*, const cuuint64_t*, const cuuint32_t*,
                             const cuuint32_t*, CUtensorMapInterleave, CUtensorMapSwizzle,
                             CUtensorMapL2promotion, CUtensorMapFloatOOBfill);

extern "C" void kernel_launch(void* const* d_in, const int* in_sizes, int n_in,
                              void* d_out, int out_size)
{
    const float* self_vecs = (const float*)d_in[0];
    const float* neigh     = (const float*)d_in[1];
    const float* W1        = (const float*)d_in[2];
    const float* b1        = (const float*)d_in[3];
    const float* Wt1       = (const float*)d_in[4];
    const float* bt1       = (const float*)d_in[5];
    const float* Wt2       = (const float*)d_in[6];
    const float* bt2       = (const float*)d_in[7];
    float* out = (float*)d_out;

    const int B = in_sizes[0] / 256;

    // encode TMA descriptor for neigh [B*32 rows x 256 cols] fp32, box 32x256, SW128
    CUtensorMap tmap;
    EncodeFn enc = nullptr;
    cudaDriverEntryPointQueryResult qr;
    cudaGetDriverEntryPointByVersion("cuTensorMapEncodeTiled", (void**)&enc, 12000,
                                     cudaEnableDefault, &qr);
    cuuint64_t gdim[2] = {256ull, (cuuint64_t)B * 32ull};
    cuuint64_t gstr[1] = {256ull * 4ull};
    cuuint32_t box[2]  = {32u, 256u};
    cuuint32_t est[2]  = {1u, 1u};
    enc(&tmap, CU_TENSOR_MAP_DATA_TYPE_FLOAT32, 2, (void*)neigh, gdim, gstr, box, est,
        CU_TENSOR_MAP_INTERLEAVE_NONE, CU_TENSOR_MAP_SWIZZLE_128B,
        CU_TENSOR_MAP_L2_PROMOTION_L2_128B, CU_TENSOR_MAP_FLOAT_OOB_FILL_NONE);

    cudaFuncSetAttribute(k1_neigh_pool, cudaFuncAttributeMaxDynamicSharedMemorySize, K1SMEM);
    k1_neigh_pool<<<148, 256, K1SMEM>>>(tmap, W1, B);

    dim3 g2(4, (B + 127) / 128);
    k2_self_gemm<<<g2, 256>>>(self_vecs, Wt2, bt2, out, B);

    k3_neigh_out<<<(B + 127) / 128, 512>>>(b1, Wt1, bt1, out, B);
}